// round 2
// baseline (speedup 1.0000x reference)
#include <cuda_runtime.h>

// Problem constants (from reference: B=2, H=8, S=2048, D=2048)
#define N_ELEM   67108864    // elements per input tensor (2*8*2048*2048)
#define N0       33554432    // elements in x[0] (first batch element)
#define K_IDX    33218888u   // exact f32 quantile index: fl(fl(0.99)*fl(n-1)) = 33218888.0, frac=0
#define SDIM     2048
#define NBATCH   16          // B*H

// ---------------- device state (re-initialized every launch; graph-safe) ----
__device__ unsigned g_hist[2][256];
__device__ unsigned g_pref[2];
__device__ unsigned g_krem[2];
__device__ unsigned g_taub[2];    // tau bit pattern (nonneg float)
__device__ unsigned g_maxres[2];  // max |resid| bit pattern
__device__ float    g_scale[2];

// ---------------- init -----------------------------------------------------
__global__ void k_init() {
    int i = threadIdx.x;
    g_hist[0][i] = 0; g_hist[1][i] = 0;
    if (i < 2) { g_pref[i] = 0; g_krem[i] = K_IDX; g_maxres[i] = 0; }
}

// ---------------- radix-select histogram pass (8 bits) ----------------------
// blockIdx.y selects tensor (0 = x1, 1 = x2). Scans x[0..N0) only.
__global__ void __launch_bounds__(256) k_hist(const float4* __restrict__ x1,
                                              const float4* __restrict__ x2,
                                              int shift) {
    const int t = blockIdx.y;
    const float4* __restrict__ x = t ? x2 : x1;
    __shared__ unsigned sh[256];
    const int tid = threadIdx.x;
    sh[tid] = 0;
    __syncthreads();
    const unsigned pref = g_pref[t];
    const int n4 = N0 / 4;                       // 8388608
    const int stride = gridDim.x * blockDim.x;   // 512*256 divides n4 -> uniform loop
    for (int i = blockIdx.x * blockDim.x + tid; i < n4; i += stride) {
        float4 v = x[i];
        const float* f = reinterpret_cast<const float*>(&v);
        #pragma unroll
        for (int j = 0; j < 4; j++) {
            unsigned u = __float_as_uint(f[j]) & 0x7fffffffu;
            bool ok = (shift == 24) || ((u >> (shift + 8)) == pref);
            unsigned bal = __ballot_sync(0xffffffffu, ok);
            if (ok) {
                unsigned b = (u >> shift) & 255u;
                unsigned peers = __match_any_sync(bal, b);
                if ((__ffs(peers) - 1) == (tid & 31))
                    atomicAdd(&sh[b], __popc(peers));
            }
        }
    }
    __syncthreads();
    if (sh[tid]) atomicAdd(&g_hist[t][tid], sh[tid]);
}

// ---------------- radix-select scan (both tensors) --------------------------
__global__ void k_scan(int shift) {
    const int tid = threadIdx.x;
    if (tid < 2) {
        const int t = tid;
        unsigned k = g_krem[t], c = 0, chosen = 255;
        for (int b = 0; b < 256; b++) {
            unsigned h = g_hist[t][b];
            if (c + h > k) { chosen = (unsigned)b; break; }
            c += h;
        }
        g_krem[t] = k - c;
        unsigned p = (g_pref[t] << 8) | chosen;
        g_pref[t] = p;
        if (shift == 0) g_taub[t] = p;   // full 32-bit value = tau bits
    }
    __syncthreads();
    g_hist[0][tid] = 0; g_hist[1][tid] = 0;   // ready for next pass
}

// ---------------- max |resid| over FULL tensor (|x| < tau strictly) ---------
__global__ void __launch_bounds__(256) k_maxres(const float4* __restrict__ x1,
                                                const float4* __restrict__ x2) {
    const int t = blockIdx.y;
    const float4* __restrict__ x = t ? x2 : x1;
    const unsigned taub = g_taub[t];
    const int tid = threadIdx.x;
    unsigned m = 0;
    const int n4 = N_ELEM / 4;                   // 16777216
    const int stride = gridDim.x * blockDim.x;   // 1024*256 divides n4
    for (int i = blockIdx.x * blockDim.x + tid; i < n4; i += stride) {
        float4 v = x[i];
        const float* f = reinterpret_cast<const float*>(&v);
        #pragma unroll
        for (int j = 0; j < 4; j++) {
            unsigned u = __float_as_uint(f[j]) & 0x7fffffffu;
            if (u < taub) m = max(m, u);
        }
    }
    m = __reduce_max_sync(0xffffffffu, m);
    __shared__ unsigned sm[8];
    if ((tid & 31) == 0) sm[tid >> 5] = m;
    __syncthreads();
    if (tid == 0) {
        #pragma unroll
        for (int w = 1; w < 8; w++) m = max(m, sm[w]);
        atomicMax(&g_maxres[t], m);
    }
}

__global__ void k_scale() {
    int t = threadIdx.x;
    if (t < 2) g_scale[t] = __fdiv_rn(__uint_as_float(g_maxres[t]), 127.0f);
}

// ---------------- quantize round-trip -> output regions 1 and 2 -------------
__global__ void __launch_bounds__(256) k_quant(const float4* __restrict__ x1,
                                               const float4* __restrict__ x2,
                                               float4* __restrict__ out) {
    const int t = blockIdx.y;
    const float4* __restrict__ x = t ? x2 : x1;
    float4* __restrict__ o = out + (size_t)(1 + t) * (N_ELEM / 4);
    const float tau = __uint_as_float(g_taub[t]);
    const float scale = g_scale[t];
    const int n4 = N_ELEM / 4;
    const int stride = gridDim.x * blockDim.x;
    for (int i = blockIdx.x * blockDim.x + threadIdx.x; i < n4; i += stride) {
        float4 v = x[i];
        float* f = reinterpret_cast<float*>(&v);
        #pragma unroll
        for (int j = 0; j < 4; j++) {
            float a = fabsf(f[j]);
            if (a < tau) {   // outlier (>= tau) reconstructs exactly as f[j]
                float q = rintf(__fdiv_rn(f[j], scale));   // round-half-even like jnp.round
                q = fminf(fmaxf(q, -128.0f), 127.0f);
                f[j] = q * scale;
            }
        }
        o[i] = v;
    }
}

// ---------------- batched SGEMM: C[g] = A[g] @ B[g], 2048^3 x16 -------------
// 128x128 block tile, BK=16, 8x8 per thread, 256 threads.
__global__ void __launch_bounds__(256) k_gemm(const float* __restrict__ A0,
                                              const float* __restrict__ B0,
                                              float* __restrict__ C0) {
    const int bz = blockIdx.z;
    const float* __restrict__ A = A0 + (size_t)bz * SDIM * SDIM;
    const float* __restrict__ Bp = B0 + (size_t)bz * SDIM * SDIM;
    float* __restrict__ C = C0 + (size_t)bz * SDIM * SDIM;

    __shared__ float As[16][132];   // [k][m], padded to kill bank conflicts
    __shared__ float Bs[16][128];   // [k][n]

    const int tid = threadIdx.x;
    const int tx = tid & 15, ty = tid >> 4;
    const int mBase = blockIdx.y * 128, nBase = blockIdx.x * 128;

    float acc[8][8];
    #pragma unroll
    for (int i = 0; i < 8; i++)
        #pragma unroll
        for (int j = 0; j < 8; j++) acc[i][j] = 0.0f;

    for (int k0 = 0; k0 < SDIM; k0 += 16) {
        // load A tile: 128 rows x 16 k = 512 float4, 2 per thread
        #pragma unroll
        for (int l = 0; l < 2; l++) {
            int idx = tid + l * 256;
            int ar = idx >> 2, ac = (idx & 3) * 4;
            float4 av = *(const float4*)(A + (size_t)(mBase + ar) * SDIM + k0 + ac);
            As[ac + 0][ar] = av.x; As[ac + 1][ar] = av.y;
            As[ac + 2][ar] = av.z; As[ac + 3][ar] = av.w;
        }
        // load B tile: 16 rows x 128 n = 512 float4, 2 per thread
        #pragma unroll
        for (int l = 0; l < 2; l++) {
            int idx = tid + l * 256;
            int br = idx >> 5, bc = (idx & 31) * 4;
            float4 bv = *(const float4*)(Bp + (size_t)(k0 + br) * SDIM + nBase + bc);
            *(float4*)&Bs[br][bc] = bv;
        }
        __syncthreads();
        #pragma unroll
        for (int kk = 0; kk < 16; kk++) {
            float4 a0 = *(const float4*)&As[kk][ty * 8];
            float4 a1 = *(const float4*)&As[kk][ty * 8 + 4];
            float4 b0 = *(const float4*)&Bs[kk][tx * 8];
            float4 b1 = *(const float4*)&Bs[kk][tx * 8 + 4];
            float a[8] = {a0.x, a0.y, a0.z, a0.w, a1.x, a1.y, a1.z, a1.w};
            float b[8] = {b0.x, b0.y, b0.z, b0.w, b1.x, b1.y, b1.z, b1.w};
            #pragma unroll
            for (int i = 0; i < 8; i++)
                #pragma unroll
                for (int j = 0; j < 8; j++)
                    acc[i][j] = fmaf(a[i], b[j], acc[i][j]);
        }
        __syncthreads();
    }

    #pragma unroll
    for (int i = 0; i < 8; i++) {
        float* cr = C + (size_t)(mBase + ty * 8 + i) * SDIM + nBase + tx * 8;
        *(float4*)cr       = make_float4(acc[i][0], acc[i][1], acc[i][2], acc[i][3]);
        *(float4*)(cr + 4) = make_float4(acc[i][4], acc[i][5], acc[i][6], acc[i][7]);
    }
}

// ---------------- launch -----------------------------------------------------
extern "C" void kernel_launch(void* const* d_in, const int* in_sizes, int n_in,
                              void* d_out, int out_size) {
    const float* x1 = (const float*)d_in[0];
    const float* x2 = (const float*)d_in[1];
    float* out = (float*)d_out;
    const float4* x1v = (const float4*)x1;
    const float4* x2v = (const float4*)x2;

    // GEMM (independent of compression) -> out[0 .. N_ELEM)
    k_gemm<<<dim3(16, 16, NBATCH), 256>>>(x1, x2, out);

    // Radix select of the exact quantile order statistic of |x[0]| (both tensors)
    k_init<<<1, 256>>>();
    for (int shift = 24; shift >= 0; shift -= 8) {
        k_hist<<<dim3(512, 2), 256>>>(x1v, x2v, shift);
        k_scan<<<1, 256>>>(shift);
    }
    // max |resid| over the full tensors, then scale = max/127
    k_maxres<<<dim3(1024, 2), 256>>>(x1v, x2v);
    k_scale<<<1, 32>>>();
    // quantize round-trip -> out[N_ELEM .. 2*N_ELEM) and out[2*N_ELEM .. 3*N_ELEM)
    // (x2's transpose cancels: stats + elementwise ops are layout-invariant)
    k_quant<<<dim3(1024, 2), 256>>>(x1v, x2v, (float4*)out);
}

// round 5
// speedup vs baseline: 1.9844x; 1.9844x over previous
#include <cuda_runtime.h>
#include <cuda_bf16.h>
#include <cstdint>

// Problem constants (B=2, H=8, S=2048, D=2048)
#define N_ELEM   67108864    // elements per input tensor
#define N0       33554432    // elements in x[0]
#define K_IDX    33218888u   // exact f32 quantile index of |x[0]| ascending
#define SDIM     2048
#define NBATCH   16

// ===================== scratch: bf16 split tensors (linear) =================
__device__ __align__(1024) __nv_bfloat16 g_Ahi[N_ELEM];   // [g][m][k]
__device__ __align__(1024) __nv_bfloat16 g_Alo[N_ELEM];
__device__ __align__(1024) __nv_bfloat16 g_Bthi[N_ELEM];  // [g][n][k] (B transposed)
__device__ __align__(1024) __nv_bfloat16 g_Btlo[N_ELEM];

// ===================== stats state (re-initialized per launch) ==============
__device__ unsigned g_hist[2][256];
__device__ unsigned g_pref[2];
__device__ unsigned g_krem[2];
__device__ unsigned g_taub[2];
__device__ unsigned g_maxres[2];
__device__ float    g_scale[2];

__global__ void k_init() {
    int i = threadIdx.x;
    g_hist[0][i] = 0; g_hist[1][i] = 0;
    if (i < 2) { g_pref[i] = 0; g_krem[i] = K_IDX; g_maxres[i] = 0; }
}

__global__ void __launch_bounds__(256) k_hist(const float4* __restrict__ x1,
                                              const float4* __restrict__ x2,
                                              int shift) {
    const int t = blockIdx.y;
    const float4* __restrict__ x = t ? x2 : x1;
    __shared__ unsigned sh[256];
    const int tid = threadIdx.x;
    sh[tid] = 0;
    __syncthreads();
    const unsigned pref = g_pref[t];
    const int n4 = N0 / 4;
    const int stride = gridDim.x * blockDim.x;
    for (int i = blockIdx.x * blockDim.x + tid; i < n4; i += stride) {
        float4 v = x[i];
        const float* f = reinterpret_cast<const float*>(&v);
        #pragma unroll
        for (int j = 0; j < 4; j++) {
            unsigned u = __float_as_uint(f[j]) & 0x7fffffffu;
            bool ok = (shift == 24) || ((u >> (shift + 8)) == pref);
            unsigned bal = __ballot_sync(0xffffffffu, ok);
            if (ok) {
                unsigned b = (u >> shift) & 255u;
                unsigned peers = __match_any_sync(bal, b);
                if ((__ffs(peers) - 1) == (tid & 31))
                    atomicAdd(&sh[b], __popc(peers));
            }
        }
    }
    __syncthreads();
    if (sh[tid]) atomicAdd(&g_hist[t][tid], sh[tid]);
}

__global__ void k_scan(int shift) {
    const int tid = threadIdx.x;
    if (tid < 2) {
        const int t = tid;
        unsigned k = g_krem[t], c = 0, chosen = 255;
        for (int b = 0; b < 256; b++) {
            unsigned h = g_hist[t][b];
            if (c + h > k) { chosen = (unsigned)b; break; }
            c += h;
        }
        g_krem[t] = k - c;
        unsigned p = (g_pref[t] << 8) | chosen;
        g_pref[t] = p;
        if (shift == 0) g_taub[t] = p;
    }
    __syncthreads();
    g_hist[0][tid] = 0; g_hist[1][tid] = 0;
}

__global__ void __launch_bounds__(256) k_maxres(const float4* __restrict__ x1,
                                                const float4* __restrict__ x2) {
    const int t = blockIdx.y;
    const float4* __restrict__ x = t ? x2 : x1;
    const unsigned taub = g_taub[t];
    const int tid = threadIdx.x;
    unsigned m = 0;
    const int n4 = N_ELEM / 4;
    const int stride = gridDim.x * blockDim.x;
    for (int i = blockIdx.x * blockDim.x + tid; i < n4; i += stride) {
        float4 v = x[i];
        const float* f = reinterpret_cast<const float*>(&v);
        #pragma unroll
        for (int j = 0; j < 4; j++) {
            unsigned u = __float_as_uint(f[j]) & 0x7fffffffu;
            if (u < taub) m = max(m, u);
        }
    }
    m = __reduce_max_sync(0xffffffffu, m);
    __shared__ unsigned sm[8];
    if ((tid & 31) == 0) sm[tid >> 5] = m;
    __syncthreads();
    if (tid == 0) {
        #pragma unroll
        for (int w = 1; w < 8; w++) m = max(m, sm[w]);
        atomicMax(&g_maxres[t], m);
    }
}

__global__ void k_scale() {
    int t = threadIdx.x;
    if (t < 2) g_scale[t] = __fdiv_rn(__uint_as_float(g_maxres[t]), 127.0f);
}

__global__ void __launch_bounds__(256) k_quant(const float4* __restrict__ x1,
                                               const float4* __restrict__ x2,
                                               float4* __restrict__ out) {
    const int t = blockIdx.y;
    const float4* __restrict__ x = t ? x2 : x1;
    float4* __restrict__ o = out + (size_t)(1 + t) * (N_ELEM / 4);
    const float tau = __uint_as_float(g_taub[t]);
    const float scale = g_scale[t];
    const int n4 = N_ELEM / 4;
    const int stride = gridDim.x * blockDim.x;
    for (int i = blockIdx.x * blockDim.x + threadIdx.x; i < n4; i += stride) {
        float4 v = x[i];
        float* f = reinterpret_cast<float*>(&v);
        #pragma unroll
        for (int j = 0; j < 4; j++) {
            float a = fabsf(f[j]);
            if (a < tau) {
                float q = rintf(__fdiv_rn(f[j], scale));
                q = fminf(fmaxf(q, -128.0f), 127.0f);
                f[j] = q * scale;
            }
        }
        o[i] = v;
    }
}

// ===== pack helpers =========================================================
__device__ __forceinline__ uint32_t pack_hi(float a, float b, float& ra, float& rb) {
    __nv_bfloat16 ha = __float2bfloat16(a), hb = __float2bfloat16(b);
    ra = a - __bfloat162float(ha);
    rb = b - __bfloat162float(hb);
    __nv_bfloat162 p; p.x = ha; p.y = hb;
    return *reinterpret_cast<uint32_t*>(&p);
}
__device__ __forceinline__ uint32_t pack_lo(float ra, float rb) {
    __nv_bfloat162 p; p.x = __float2bfloat16(ra); p.y = __float2bfloat16(rb);
    return *reinterpret_cast<uint32_t*>(&p);
}

// ===== A: f32 [g][m][k] -> hi/lo bf16 (linear) ==============================
__global__ void __launch_bounds__(256) k_convA(const float4* __restrict__ x) {
    const int stride = gridDim.x * blockDim.x;
    for (int i = blockIdx.x * blockDim.x + threadIdx.x; i < N_ELEM / 8; i += stride) {
        float4 v0 = x[2 * i], v1 = x[2 * i + 1];
        float f[8] = {v0.x, v0.y, v0.z, v0.w, v1.x, v1.y, v1.z, v1.w};
        uint32_t hi[4], lo[4];
        #pragma unroll
        for (int j = 0; j < 4; j++) {
            float ra, rb;
            hi[j] = pack_hi(f[2 * j], f[2 * j + 1], ra, rb);
            lo[j] = pack_lo(ra, rb);
        }
        reinterpret_cast<uint4*>(g_Ahi)[i] = make_uint4(hi[0], hi[1], hi[2], hi[3]);
        reinterpret_cast<uint4*>(g_Alo)[i] = make_uint4(lo[0], lo[1], lo[2], lo[3]);
    }
}

// ===== B: f32 [g][k][n] -> transposed hi/lo bf16 [g][n][k] ==================
__global__ void __launch_bounds__(256) k_convB(const float* __restrict__ x) {
    __shared__ float t[32][33];
    const int g = blockIdx.z;
    const float* B = x + (size_t)g * SDIM * SDIM;
    const int n0 = blockIdx.x * 32, k0 = blockIdx.y * 32;
    const int tx = threadIdx.x, ty = threadIdx.y;
    #pragma unroll
    for (int j = 0; j < 32; j += 8)
        t[ty + j][tx] = B[(size_t)(k0 + ty + j) * SDIM + n0 + tx];
    __syncthreads();
    #pragma unroll
    for (int j = 0; j < 32; j += 8) {
        int n = n0 + ty + j, k = k0 + tx;
        float v = t[tx][ty + j];
        float r, rd;
        uint32_t hu;
        {
            __nv_bfloat16 h = __float2bfloat16(v);
            r = v - __bfloat162float(h);
            __nv_bfloat162 hp; hp.x = h; hp.y = h;  // scalar path below
            hu = 0; (void)hp;
            size_t o = (size_t)g * SDIM * SDIM + (size_t)n * SDIM + k;
            g_Bthi[o] = h;
            g_Btlo[o] = __float2bfloat16(r);
            (void)rd; (void)hu;
        }
    }
}

// ===== tensor-core GEMM via mma.sync (HMMA), 3-term bf16 split ==============
// CTA 128x128, BK=32, 2-stage cp.async double buffer, 8 warps (4m x 2n),
// warp tile 32x64, mma.m16n8k16. Swizzle: 16B unit u stored at u^((row>>1)&3).
#define BM 128
#define BN 128
#define BK 32
#define KSTEPS 192   // 3 terms * 64 k-chunks

__device__ __forceinline__ uint32_t smem_u32(const void* p) {
    uint32_t a;
    asm("{ .reg .u64 t; cvta.to.shared.u64 t, %1; cvt.u32.u64 %0, t; }" : "=r"(a) : "l"(p));
    return a;
}
__device__ __forceinline__ void cp_async16(uint32_t dst, const void* src) {
    asm volatile("cp.async.cg.shared.global [%0], [%1], 16;"
                 :: "r"(dst), "l"(__cvta_generic_to_global(src)) : "memory");
}
__device__ __forceinline__ void ldsm_x4(uint32_t* r, uint32_t addr) {
    asm volatile("ldmatrix.sync.aligned.m8n8.x4.shared.b16 {%0,%1,%2,%3}, [%4];"
                 : "=r"(r[0]), "=r"(r[1]), "=r"(r[2]), "=r"(r[3]) : "r"(addr));
}
__device__ __forceinline__ void mma16816(float* d, const uint32_t* a, uint32_t b0, uint32_t b1) {
    asm volatile("mma.sync.aligned.m16n8k16.row.col.f32.bf16.bf16.f32 "
                 "{%0,%1,%2,%3}, {%4,%5,%6,%7}, {%8,%9}, {%0,%1,%2,%3};"
                 : "+f"(d[0]), "+f"(d[1]), "+f"(d[2]), "+f"(d[3])
                 : "r"(a[0]), "r"(a[1]), "r"(a[2]), "r"(a[3]), "r"(b0), "r"(b1));
}

__global__ void __launch_bounds__(256, 2) k_gemm_mma(float* __restrict__ C0) {
    __shared__ __align__(1024) __nv_bfloat16 As[2][BM * BK];
    __shared__ __align__(1024) __nv_bfloat16 Bs[2][BN * BK];

    const int tid = threadIdx.x, lane = tid & 31, w = tid >> 5;
    const int wm = w >> 1, wn = w & 1;
    const int g = blockIdx.z, bm = blockIdx.y, bn = blockIdx.x;
    const size_t gbase = (size_t)g * SDIM * SDIM;

    const uint32_t sA = smem_u32(As), sB = smem_u32(Bs);

    float acc[2][8][4];
    #pragma unroll
    for (int i = 0; i < 2; i++)
        #pragma unroll
        for (int j = 0; j < 8; j++)
            #pragma unroll
            for (int q = 0; q < 4; q++) acc[i][j][q] = 0.0f;

    const int ldRow = tid >> 2, ldUnit = tid & 3;

    // issue cp.async loads of k-chunk kt into stage st
    auto issue = [&](int kt, int st) {
        const int term = kt >> 6, kk = kt & 63;
        const __nv_bfloat16* Abase = ((term < 2) ? g_Ahi : g_Alo)
                                     + gbase + (size_t)(bm * 128) * SDIM + kk * 32;
        const __nv_bfloat16* Bbase = ((term == 1) ? g_Btlo : g_Bthi)
                                     + gbase + (size_t)(bn * 128) * SDIM + kk * 32;
        #pragma unroll
        for (int it = 0; it < 2; it++) {
            const int r = ldRow + it * 64;
            const uint32_t du = (uint32_t)(ldUnit ^ ((r >> 1) & 3));
            cp_async16(sA + (uint32_t)st * (BM * BK * 2) + (uint32_t)r * 64 + du * 16,
                       Abase + (size_t)r * SDIM + ldUnit * 8);
            cp_async16(sB + (uint32_t)st * (BN * BK * 2) + (uint32_t)r * 64 + du * 16,
                       Bbase + (size_t)r * SDIM + ldUnit * 8);
        }
        asm volatile("cp.async.commit_group;" ::: "memory");
    };

    issue(0, 0);
    for (int kt = 0; kt < KSTEPS; kt++) {
        if (kt + 1 < KSTEPS) {
            issue(kt + 1, (kt + 1) & 1);
            asm volatile("cp.async.wait_group 1;" ::: "memory");
        } else {
            asm volatile("cp.async.wait_group 0;" ::: "memory");
        }
        __syncthreads();

        const int st = kt & 1;
        const uint32_t aSt = sA + (uint32_t)st * (BM * BK * 2);
        const uint32_t bSt = sB + (uint32_t)st * (BN * BK * 2);
        #pragma unroll
        for (int k16 = 0; k16 < 2; k16++) {
            const int ku = k16 * 2 + (lane >> 4);
            uint32_t a[2][4];
            #pragma unroll
            for (int mt = 0; mt < 2; mt++) {
                const int r = wm * 32 + mt * 16 + (lane & 15);
                ldsm_x4(a[mt], aSt + (uint32_t)r * 64 + (uint32_t)((ku ^ ((r >> 1) & 3)) * 16));
            }
            uint32_t b[4][4];
            #pragma unroll
            for (int ng = 0; ng < 4; ng++) {
                const int r = wn * 64 + ng * 16 + (lane & 15);
                ldsm_x4(b[ng], bSt + (uint32_t)r * 64 + (uint32_t)((ku ^ ((r >> 1) & 3)) * 16));
            }
            #pragma unroll
            for (int mt = 0; mt < 2; mt++)
                #pragma unroll
                for (int nt = 0; nt < 8; nt++)
                    mma16816(acc[mt][nt], a[mt], b[nt >> 1][nt & 1], b[nt >> 1][(nt & 1) + 2]);
        }
        __syncthreads();
    }

    // epilogue
    float* C = C0 + gbase;
    const int rB = bm * 128 + wm * 32 + (lane >> 2);
    const int cB = bn * 128 + wn * 64 + (lane & 3) * 2;
    #pragma unroll
    for (int mt = 0; mt < 2; mt++)
        #pragma unroll
        for (int nt = 0; nt < 8; nt++) {
            const int row = rB + mt * 16, col = cB + nt * 8;
            *reinterpret_cast<float2*>(C + (size_t)row * SDIM + col) =
                make_float2(acc[mt][nt][0], acc[mt][nt][1]);
            *reinterpret_cast<float2*>(C + (size_t)(row + 8) * SDIM + col) =
                make_float2(acc[mt][nt][2], acc[mt][nt][3]);
        }
}

// ===================== launch ==============================================
extern "C" void kernel_launch(void* const* d_in, const int* in_sizes, int n_in,
                              void* d_out, int out_size) {
    const float* x1 = (const float*)d_in[0];
    const float* x2 = (const float*)d_in[1];
    float* out = (float*)d_out;
    const float4* x1v = (const float4*)x1;
    const float4* x2v = (const float4*)x2;

    // One-time stream/event resources for fork-join overlap (work per call is
    // identical every call; only resource handles are persistent).
    static cudaStream_t s2 = nullptr;
    static cudaEvent_t evF = nullptr, evJ = nullptr;
    static int ready = 0;
    if (ready == 0) {
        bool ok = (cudaStreamCreateWithFlags(&s2, cudaStreamNonBlocking) == cudaSuccess) &&
                  (cudaEventCreateWithFlags(&evF, cudaEventDisableTiming) == cudaSuccess) &&
                  (cudaEventCreateWithFlags(&evJ, cudaEventDisableTiming) == cudaSuccess);
        ready = ok ? 1 : -1;
    }

    cudaStream_t sStats = (ready == 1) ? s2 : (cudaStream_t)0;
    if (ready == 1) {
        cudaEventRecord(evF, 0);
        cudaStreamWaitEvent(s2, evF, 0);
    }

    // ---- main stream: conversions + tensor-core GEMM -> out region 0 ----
    k_convA<<<1024, 256>>>(x1v);
    k_convB<<<dim3(64, 64, NBATCH), dim3(32, 8)>>>(x2);
    k_gemm_mma<<<dim3(16, 16, NBATCH), 256>>>(out);

    // ---- stats stream: quantile + quantize -> out regions 1, 2 ----
    k_init<<<1, 256, 0, sStats>>>();
    for (int shift = 24; shift >= 0; shift -= 8) {
        k_hist<<<dim3(512, 2), 256, 0, sStats>>>(x1v, x2v, shift);
        k_scan<<<1, 256, 0, sStats>>>(shift);
    }
    k_maxres<<<dim3(1024, 2), 256, 0, sStats>>>(x1v, x2v);
    k_scale<<<1, 32, 0, sStats>>>();
    k_quant<<<dim3(1024, 2), 256, 0, sStats>>>(x1v, x2v, (float4*)out);

    if (ready == 1) {
        cudaEventRecord(evJ, s2);
        cudaStreamWaitEvent((cudaStream_t)0, evJ, 0);
    }
}

// round 6
// speedup vs baseline: 2.0420x; 1.0290x over previous
#include <cuda_runtime.h>
#include <cuda_bf16.h>
#include <cstdint>

// Problem constants (B=2, H=8, S=2048, D=2048)
#define N_ELEM   67108864    // elements per input tensor
#define N0       33554432    // elements in x[0]
#define K_IDX    33218888u   // exact f32 quantile index of |x[0]| ascending
#define SDIM     2048
#define NBATCH   16

// ===================== scratch: bf16 split tensors (linear) =================
__device__ __align__(1024) __nv_bfloat16 g_Ahi[N_ELEM];   // [g][m][k]
__device__ __align__(1024) __nv_bfloat16 g_Alo[N_ELEM];
__device__ __align__(1024) __nv_bfloat16 g_Bthi[N_ELEM];  // [g][n][k] (B transposed)
__device__ __align__(1024) __nv_bfloat16 g_Btlo[N_ELEM];

// ===================== stats state (re-initialized per launch) ==============
__device__ unsigned g_hist[2][256];
__device__ unsigned g_pref[2];
__device__ unsigned g_krem[2];
__device__ unsigned g_taub[2];
__device__ unsigned g_maxres[2];
__device__ float    g_scale[2];

__global__ void k_init() {
    int i = threadIdx.x;
    g_hist[0][i] = 0; g_hist[1][i] = 0;
    if (i < 2) { g_pref[i] = 0; g_krem[i] = K_IDX; g_maxres[i] = 0; }
}

__global__ void __launch_bounds__(256) k_hist(const float4* __restrict__ x1,
                                              const float4* __restrict__ x2,
                                              int shift) {
    const int t = blockIdx.y;
    const float4* __restrict__ x = t ? x2 : x1;
    __shared__ unsigned sh[256];
    const int tid = threadIdx.x;
    sh[tid] = 0;
    __syncthreads();
    const unsigned pref = g_pref[t];
    const int n4 = N0 / 4;
    const int stride = gridDim.x * blockDim.x;
    for (int i = blockIdx.x * blockDim.x + tid; i < n4; i += stride) {
        float4 v = x[i];
        const float* f = reinterpret_cast<const float*>(&v);
        #pragma unroll
        for (int j = 0; j < 4; j++) {
            unsigned u = __float_as_uint(f[j]) & 0x7fffffffu;
            bool ok = (shift == 24) || ((u >> (shift + 8)) == pref);
            unsigned bal = __ballot_sync(0xffffffffu, ok);
            if (ok) {
                unsigned b = (u >> shift) & 255u;
                unsigned peers = __match_any_sync(bal, b);
                if ((__ffs(peers) - 1) == (tid & 31))
                    atomicAdd(&sh[b], __popc(peers));
            }
        }
    }
    __syncthreads();
    if (sh[tid]) atomicAdd(&g_hist[t][tid], sh[tid]);
}

__global__ void k_scan(int shift) {
    const int tid = threadIdx.x;
    if (tid < 2) {
        const int t = tid;
        unsigned k = g_krem[t], c = 0, chosen = 255;
        for (int b = 0; b < 256; b++) {
            unsigned h = g_hist[t][b];
            if (c + h > k) { chosen = (unsigned)b; break; }
            c += h;
        }
        g_krem[t] = k - c;
        unsigned p = (g_pref[t] << 8) | chosen;
        g_pref[t] = p;
        if (shift == 0) g_taub[t] = p;
    }
    __syncthreads();
    g_hist[0][tid] = 0; g_hist[1][tid] = 0;
}

__global__ void __launch_bounds__(256) k_maxres(const float4* __restrict__ x1,
                                                const float4* __restrict__ x2) {
    const int t = blockIdx.y;
    const float4* __restrict__ x = t ? x2 : x1;
    const unsigned taub = g_taub[t];
    const int tid = threadIdx.x;
    unsigned m = 0;
    const int n4 = N_ELEM / 4;
    const int stride = gridDim.x * blockDim.x;
    for (int i = blockIdx.x * blockDim.x + tid; i < n4; i += stride) {
        float4 v = x[i];
        const float* f = reinterpret_cast<const float*>(&v);
        #pragma unroll
        for (int j = 0; j < 4; j++) {
            unsigned u = __float_as_uint(f[j]) & 0x7fffffffu;
            if (u < taub) m = max(m, u);
        }
    }
    m = __reduce_max_sync(0xffffffffu, m);
    __shared__ unsigned sm[8];
    if ((tid & 31) == 0) sm[tid >> 5] = m;
    __syncthreads();
    if (tid == 0) {
        #pragma unroll
        for (int w = 1; w < 8; w++) m = max(m, sm[w]);
        atomicMax(&g_maxres[t], m);
    }
}

__global__ void k_scale() {
    int t = threadIdx.x;
    if (t < 2) g_scale[t] = __fdiv_rn(__uint_as_float(g_maxres[t]), 127.0f);
}

__global__ void __launch_bounds__(256) k_quant(const float4* __restrict__ x1,
                                               const float4* __restrict__ x2,
                                               float4* __restrict__ out) {
    const int t = blockIdx.y;
    const float4* __restrict__ x = t ? x2 : x1;
    float4* __restrict__ o = out + (size_t)(1 + t) * (N_ELEM / 4);
    const float tau = __uint_as_float(g_taub[t]);
    const float scale = g_scale[t];
    const int n4 = N_ELEM / 4;
    const int stride = gridDim.x * blockDim.x;
    for (int i = blockIdx.x * blockDim.x + threadIdx.x; i < n4; i += stride) {
        float4 v = x[i];
        float* f = reinterpret_cast<float*>(&v);
        #pragma unroll
        for (int j = 0; j < 4; j++) {
            float a = fabsf(f[j]);
            if (a < tau) {
                float q = rintf(__fdiv_rn(f[j], scale));
                q = fminf(fmaxf(q, -128.0f), 127.0f);
                f[j] = q * scale;
            }
        }
        o[i] = v;
    }
}

// ===== pack helpers =========================================================
__device__ __forceinline__ uint32_t pack_hi(float a, float b, float& ra, float& rb) {
    __nv_bfloat16 ha = __float2bfloat16(a), hb = __float2bfloat16(b);
    ra = a - __bfloat162float(ha);
    rb = b - __bfloat162float(hb);
    __nv_bfloat162 p; p.x = ha; p.y = hb;
    return *reinterpret_cast<uint32_t*>(&p);
}
__device__ __forceinline__ uint32_t pack_lo(float ra, float rb) {
    __nv_bfloat162 p; p.x = __float2bfloat16(ra); p.y = __float2bfloat16(rb);
    return *reinterpret_cast<uint32_t*>(&p);
}

// ===== A: f32 [g][m][k] -> hi/lo bf16 (linear) ==============================
__global__ void __launch_bounds__(256) k_convA(const float4* __restrict__ x) {
    const int stride = gridDim.x * blockDim.x;
    for (int i = blockIdx.x * blockDim.x + threadIdx.x; i < N_ELEM / 8; i += stride) {
        float4 v0 = x[2 * i], v1 = x[2 * i + 1];
        float f[8] = {v0.x, v0.y, v0.z, v0.w, v1.x, v1.y, v1.z, v1.w};
        uint32_t hi[4], lo[4];
        #pragma unroll
        for (int j = 0; j < 4; j++) {
            float ra, rb;
            hi[j] = pack_hi(f[2 * j], f[2 * j + 1], ra, rb);
            lo[j] = pack_lo(ra, rb);
        }
        reinterpret_cast<uint4*>(g_Ahi)[i] = make_uint4(hi[0], hi[1], hi[2], hi[3]);
        reinterpret_cast<uint4*>(g_Alo)[i] = make_uint4(lo[0], lo[1], lo[2], lo[3]);
    }
}

// ===== B: f32 [g][k][n] -> transposed hi/lo bf16 [g][n][k] ==================
__global__ void __launch_bounds__(256) k_convB(const float* __restrict__ x) {
    __shared__ float t[32][33];
    const int g = blockIdx.z;
    const float* B = x + (size_t)g * SDIM * SDIM;
    const int n0 = blockIdx.x * 32, k0 = blockIdx.y * 32;
    const int tx = threadIdx.x, ty = threadIdx.y;
    #pragma unroll
    for (int j = 0; j < 32; j += 8)
        t[ty + j][tx] = B[(size_t)(k0 + ty + j) * SDIM + n0 + tx];
    __syncthreads();
    #pragma unroll
    for (int j = 0; j < 32; j += 8) {
        int n = n0 + ty + j, k = k0 + tx;
        float v = t[tx][ty + j];
        __nv_bfloat16 h = __float2bfloat16(v);
        size_t o = (size_t)g * SDIM * SDIM + (size_t)n * SDIM + k;
        g_Bthi[o] = h;
        g_Btlo[o] = __float2bfloat16(v - __bfloat162float(h));
    }
}

// ===== tensor-core GEMM via mma.sync (HMMA), 3-term bf16 split ==============
// CTA 128x128, BK=32, 3-stage cp.async pipeline, 4 warps (2m x 2n),
// warp tile 64x64, mma.m16n8k16, 1 syncthreads per k-iter.
// Swizzle: 16B unit u of row r stored at u ^ ((r>>1)&3).
#define BM 128
#define BN 128
#define BK 32
#define KSTEPS 192   // 3 terms * 64 k-chunks
#define STAGES 3

__device__ __forceinline__ uint32_t smem_u32(const void* p) {
    uint32_t a;
    asm("{ .reg .u64 t; cvta.to.shared.u64 t, %1; cvt.u32.u64 %0, t; }" : "=r"(a) : "l"(p));
    return a;
}
__device__ __forceinline__ void cp_async16(uint32_t dst, const void* src) {
    asm volatile("cp.async.cg.shared.global [%0], [%1], 16;"
                 :: "r"(dst), "l"(__cvta_generic_to_global(src)) : "memory");
}
__device__ __forceinline__ void ldsm_x4(uint32_t* r, uint32_t addr) {
    asm volatile("ldmatrix.sync.aligned.m8n8.x4.shared.b16 {%0,%1,%2,%3}, [%4];"
                 : "=r"(r[0]), "=r"(r[1]), "=r"(r[2]), "=r"(r[3]) : "r"(addr));
}
__device__ __forceinline__ void mma16816(float* d, const uint32_t* a, uint32_t b0, uint32_t b1) {
    asm volatile("mma.sync.aligned.m16n8k16.row.col.f32.bf16.bf16.f32 "
                 "{%0,%1,%2,%3}, {%4,%5,%6,%7}, {%8,%9}, {%0,%1,%2,%3};"
                 : "+f"(d[0]), "+f"(d[1]), "+f"(d[2]), "+f"(d[3])
                 : "r"(a[0]), "r"(a[1]), "r"(a[2]), "r"(a[3]), "r"(b0), "r"(b1));
}

__global__ void __launch_bounds__(128, 2) k_gemm_mma(float* __restrict__ C0) {
    __shared__ __align__(1024) __nv_bfloat16 As[STAGES][BM * BK];  // 3 x 8KB
    __shared__ __align__(1024) __nv_bfloat16 Bs[STAGES][BN * BK];  // 3 x 8KB

    const int tid = threadIdx.x, lane = tid & 31, w = tid >> 5;
    const int wm = w >> 1, wn = w & 1;
    const int g = blockIdx.z, bm = blockIdx.y, bn = blockIdx.x;
    const size_t gbase = (size_t)g * SDIM * SDIM;

    const uint32_t sA = smem_u32(As), sB = smem_u32(Bs);

    float acc[4][8][4];
    #pragma unroll
    for (int i = 0; i < 4; i++)
        #pragma unroll
        for (int j = 0; j < 8; j++)
            #pragma unroll
            for (int q = 0; q < 4; q++) acc[i][j][q] = 0.0f;

    const int ldRow = tid >> 2, ldUnit = tid & 3;   // 32 rows x 4 units per pass

    auto issue = [&](int kt, int st) {
        const int term = kt >> 6, kk = kt & 63;
        const __nv_bfloat16* Abase = ((term < 2) ? g_Ahi : g_Alo)
                                     + gbase + (size_t)(bm * 128) * SDIM + kk * 32;
        const __nv_bfloat16* Bbase = ((term == 1) ? g_Btlo : g_Bthi)
                                     + gbase + (size_t)(bn * 128) * SDIM + kk * 32;
        #pragma unroll
        for (int it = 0; it < 4; it++) {
            const int r = ldRow + it * 32;
            const uint32_t du = (uint32_t)(ldUnit ^ ((r >> 1) & 3));
            cp_async16(sA + (uint32_t)st * (BM * BK * 2) + (uint32_t)r * 64 + du * 16,
                       Abase + (size_t)r * SDIM + ldUnit * 8);
            cp_async16(sB + (uint32_t)st * (BN * BK * 2) + (uint32_t)r * 64 + du * 16,
                       Bbase + (size_t)r * SDIM + ldUnit * 8);
        }
        asm volatile("cp.async.commit_group;" ::: "memory");
    };

    issue(0, 0);
    issue(1, 1);

    for (int kt = 0; kt < KSTEPS; kt++) {
        if (kt < KSTEPS - 1)
            asm volatile("cp.async.wait_group 1;" ::: "memory");
        else
            asm volatile("cp.async.wait_group 0;" ::: "memory");
        __syncthreads();   // stage kt%3 visible to all; all reads of kt-1 done

        const int st = kt % STAGES;
        const uint32_t aSt = sA + (uint32_t)st * (BM * BK * 2);
        const uint32_t bSt = sB + (uint32_t)st * (BN * BK * 2);
        #pragma unroll
        for (int k16 = 0; k16 < 2; k16++) {
            const int ku = k16 * 2 + (lane >> 4);
            uint32_t a[4][4];
            #pragma unroll
            for (int mt = 0; mt < 4; mt++) {
                const int r = wm * 64 + mt * 16 + (lane & 15);
                ldsm_x4(a[mt], aSt + (uint32_t)r * 64 + (uint32_t)((ku ^ ((r >> 1) & 3)) * 16));
            }
            uint32_t b[4][4];
            #pragma unroll
            for (int ng = 0; ng < 4; ng++) {
                const int r = wn * 64 + ng * 16 + (lane & 15);
                ldsm_x4(b[ng], bSt + (uint32_t)r * 64 + (uint32_t)((ku ^ ((r >> 1) & 3)) * 16));
            }
            #pragma unroll
            for (int mt = 0; mt < 4; mt++)
                #pragma unroll
                for (int nt = 0; nt < 8; nt++)
                    mma16816(acc[mt][nt], a[mt], b[nt >> 1][nt & 1], b[nt >> 1][(nt & 1) + 2]);
        }
        // refill stage (kt+2)%3 == (kt-1)%3: all reads of it finished before
        // this iteration's __syncthreads, so the overwrite is safe.
        if (kt + 2 < KSTEPS) issue(kt + 2, (kt + 2) % STAGES);
    }

    // epilogue
    float* C = C0 + gbase;
    #pragma unroll
    for (int mt = 0; mt < 4; mt++)
        #pragma unroll
        for (int nt = 0; nt < 8; nt++) {
            const int row = bm * 128 + wm * 64 + mt * 16 + (lane >> 2);
            const int col = bn * 128 + wn * 64 + nt * 8 + (lane & 3) * 2;
            *reinterpret_cast<float2*>(C + (size_t)row * SDIM + col) =
                make_float2(acc[mt][nt][0], acc[mt][nt][1]);
            *reinterpret_cast<float2*>(C + (size_t)(row + 8) * SDIM + col) =
                make_float2(acc[mt][nt][2], acc[mt][nt][3]);
        }
}

// ===================== launch ==============================================
extern "C" void kernel_launch(void* const* d_in, const int* in_sizes, int n_in,
                              void* d_out, int out_size) {
    const float* x1 = (const float*)d_in[0];
    const float* x2 = (const float*)d_in[1];
    float* out = (float*)d_out;
    const float4* x1v = (const float4*)x1;
    const float4* x2v = (const float4*)x2;

    // One-time stream/event resources for fork-join overlap (work per call is
    // identical every call; only resource handles are persistent).
    static cudaStream_t s2 = nullptr;
    static cudaEvent_t evF = nullptr, evJ = nullptr;
    static int ready = 0;
    if (ready == 0) {
        bool ok = (cudaStreamCreateWithFlags(&s2, cudaStreamNonBlocking) == cudaSuccess) &&
                  (cudaEventCreateWithFlags(&evF, cudaEventDisableTiming) == cudaSuccess) &&
                  (cudaEventCreateWithFlags(&evJ, cudaEventDisableTiming) == cudaSuccess);
        ready = ok ? 1 : -1;
    }

    cudaStream_t sStats = (ready == 1) ? s2 : (cudaStream_t)0;
    if (ready == 1) {
        cudaEventRecord(evF, 0);
        cudaStreamWaitEvent(s2, evF, 0);
    }

    // ---- main stream: conversions + tensor-core GEMM -> out region 0 ----
    k_convA<<<1024, 256>>>(x1v);
    k_convB<<<dim3(64, 64, NBATCH), dim3(32, 8)>>>(x2);
    k_gemm_mma<<<dim3(16, 16, NBATCH), 128>>>(out);

    // ---- stats stream: quantile + quantize -> out regions 1, 2 ----
    k_init<<<1, 256, 0, sStats>>>();
    for (int shift = 24; shift >= 0; shift -= 8) {
        k_hist<<<dim3(512, 2), 256, 0, sStats>>>(x1v, x2v, shift);
        k_scan<<<1, 256, 0, sStats>>>(shift);
    }
    k_maxres<<<dim3(1024, 2), 256, 0, sStats>>>(x1v, x2v);
    k_scale<<<1, 32, 0, sStats>>>();
    k_quant<<<dim3(1024, 2), 256, 0, sStats>>>(x1v, x2v, (float4*)out);

    if (ready == 1) {
        cudaEventRecord(evJ, s2);
        cudaStreamWaitEvent((cudaStream_t)0, evJ, 0);
    }
}

// round 8
// speedup vs baseline: 2.7079x; 1.3261x over previous
#include <cuda_runtime.h>
#include <cuda_fp16.h>
#include <cstdint>

// Problem constants (B=2, H=8, S=2048, D=2048)
#define N_ELEM   67108864    // elements per input tensor
#define N0       33554432    // elements in x[0]
#define K_IDX    33218888u   // exact f32 quantile index of |x[0]| ascending
#define SDIM     2048
#define NBATCH   16

// ===================== scratch: fp16 split tensors (linear) =================
__device__ __align__(1024) __half g_Ahi[N_ELEM];   // [g][m][k]  fp16(x1)
__device__ __align__(1024) __half g_Bthi[N_ELEM];  // [g][n][k]  fp16(x2^T)
__device__ __align__(1024) __half g_Btlo[N_ELEM];  // [g][n][k]  fp16((x2^T - hi)*1024)

// ===================== stats state (re-initialized per launch) ==============
__device__ unsigned g_hist[2][256];
__device__ unsigned g_pref[2];
__device__ unsigned g_krem[2];
__device__ unsigned g_taub[2];
__device__ unsigned g_maxres[2];
__device__ float    g_scale[2];

__global__ void k_init() {
    int i = threadIdx.x;
    g_hist[0][i] = 0; g_hist[1][i] = 0;
    if (i < 2) { g_pref[i] = 0; g_krem[i] = K_IDX; g_maxres[i] = 0; }
}

__global__ void __launch_bounds__(256) k_hist(const float4* __restrict__ x1,
                                              const float4* __restrict__ x2,
                                              int shift) {
    const int t = blockIdx.y;
    const float4* __restrict__ x = t ? x2 : x1;
    __shared__ unsigned sh[256];
    const int tid = threadIdx.x;
    sh[tid] = 0;
    __syncthreads();
    const unsigned pref = g_pref[t];
    const int n4 = N0 / 4;
    const int stride = gridDim.x * blockDim.x;
    for (int i = blockIdx.x * blockDim.x + tid; i < n4; i += stride) {
        float4 v = x[i];
        const float* f = reinterpret_cast<const float*>(&v);
        #pragma unroll
        for (int j = 0; j < 4; j++) {
            unsigned u = __float_as_uint(f[j]) & 0x7fffffffu;
            bool ok = (shift == 24) || ((u >> (shift + 8)) == pref);
            unsigned bal = __ballot_sync(0xffffffffu, ok);
            if (ok) {
                unsigned b = (u >> shift) & 255u;
                unsigned peers = __match_any_sync(bal, b);
                if ((__ffs(peers) - 1) == (tid & 31))
                    atomicAdd(&sh[b], __popc(peers));
            }
        }
    }
    __syncthreads();
    if (sh[tid]) atomicAdd(&g_hist[t][tid], sh[tid]);
}

__global__ void k_scan(int shift) {
    const int tid = threadIdx.x;
    if (tid < 2) {
        const int t = tid;
        unsigned k = g_krem[t], c = 0, chosen = 255;
        for (int b = 0; b < 256; b++) {
            unsigned h = g_hist[t][b];
            if (c + h > k) { chosen = (unsigned)b; break; }
            c += h;
        }
        g_krem[t] = k - c;
        unsigned p = (g_pref[t] << 8) | chosen;
        g_pref[t] = p;
        if (shift == 0) g_taub[t] = p;
    }
    __syncthreads();
    g_hist[0][tid] = 0; g_hist[1][tid] = 0;
}

__global__ void __launch_bounds__(256) k_maxres(const float4* __restrict__ x1,
                                                const float4* __restrict__ x2) {
    const int t = blockIdx.y;
    const float4* __restrict__ x = t ? x2 : x1;
    const unsigned taub = g_taub[t];
    const int tid = threadIdx.x;
    unsigned m = 0;
    const int n4 = N_ELEM / 4;
    const int stride = gridDim.x * blockDim.x;
    for (int i = blockIdx.x * blockDim.x + tid; i < n4; i += stride) {
        float4 v = x[i];
        const float* f = reinterpret_cast<const float*>(&v);
        #pragma unroll
        for (int j = 0; j < 4; j++) {
            unsigned u = __float_as_uint(f[j]) & 0x7fffffffu;
            if (u < taub) m = max(m, u);
        }
    }
    m = __reduce_max_sync(0xffffffffu, m);
    __shared__ unsigned sm[8];
    if ((tid & 31) == 0) sm[tid >> 5] = m;
    __syncthreads();
    if (tid == 0) {
        #pragma unroll
        for (int w = 1; w < 8; w++) m = max(m, sm[w]);
        atomicMax(&g_maxres[t], m);
    }
}

__global__ void k_scale() {
    int t = threadIdx.x;
    if (t < 2) g_scale[t] = __fdiv_rn(__uint_as_float(g_maxres[t]), 127.0f);
}

__global__ void __launch_bounds__(256) k_quant(const float4* __restrict__ x1,
                                               const float4* __restrict__ x2,
                                               float4* __restrict__ out) {
    const int t = blockIdx.y;
    const float4* __restrict__ x = t ? x2 : x1;
    float4* __restrict__ o = out + (size_t)(1 + t) * (N_ELEM / 4);
    const float tau = __uint_as_float(g_taub[t]);
    const float scale = g_scale[t];
    const int n4 = N_ELEM / 4;
    const int stride = gridDim.x * blockDim.x;
    for (int i = blockIdx.x * blockDim.x + threadIdx.x; i < n4; i += stride) {
        float4 v = x[i];
        float* f = reinterpret_cast<float*>(&v);
        #pragma unroll
        for (int j = 0; j < 4; j++) {
            float a = fabsf(f[j]);
            if (a < tau) {
                float q = rintf(__fdiv_rn(f[j], scale));
                q = fminf(fmaxf(q, -128.0f), 127.0f);
                f[j] = q * scale;
            }
        }
        o[i] = v;
    }
}

// half2 -> u32 bit cast (no intrinsic exists for this)
__device__ __forceinline__ uint32_t h2_as_u32(__half2 h) {
    union { __half2 h; uint32_t u; } c;
    c.h = h;
    return c.u;
}

// ===== A: f32 [g][m][k] -> fp16 (linear, hi only) ===========================
__global__ void __launch_bounds__(256) k_convA(const float4* __restrict__ x) {
    const int stride = gridDim.x * blockDim.x;
    for (int i = blockIdx.x * blockDim.x + threadIdx.x; i < N_ELEM / 8; i += stride) {
        float4 v0 = x[2 * i], v1 = x[2 * i + 1];
        uint32_t h[4];
        h[0] = h2_as_u32(__floats2half2_rn(v0.x, v0.y));
        h[1] = h2_as_u32(__floats2half2_rn(v0.z, v0.w));
        h[2] = h2_as_u32(__floats2half2_rn(v1.x, v1.y));
        h[3] = h2_as_u32(__floats2half2_rn(v1.z, v1.w));
        reinterpret_cast<uint4*>(g_Ahi)[i] = make_uint4(h[0], h[1], h[2], h[3]);
    }
}

// ===== B: f32 [g][k][n] -> transposed fp16 hi + scaled-residual lo ==========
__global__ void __launch_bounds__(256) k_convB(const float* __restrict__ x) {
    __shared__ float t[32][33];
    const int g = blockIdx.z;
    const float* B = x + (size_t)g * SDIM * SDIM;
    const int n0 = blockIdx.x * 32, k0 = blockIdx.y * 32;
    const int tx = threadIdx.x, ty = threadIdx.y;
    #pragma unroll
    for (int j = 0; j < 32; j += 8)
        t[ty + j][tx] = B[(size_t)(k0 + ty + j) * SDIM + n0 + tx];
    __syncthreads();
    #pragma unroll
    for (int j = 0; j < 32; j += 8) {
        int n = n0 + ty + j, k = k0 + tx;
        float v = t[tx][ty + j];
        __half h = __float2half_rn(v);
        size_t o = (size_t)g * SDIM * SDIM + (size_t)n * SDIM + k;
        g_Bthi[o] = h;
        g_Btlo[o] = __float2half_rn((v - __half2float(h)) * 1024.0f);
    }
}

// ===== tensor-core GEMM via mma.sync (HMMA), 2-term fp16 asymmetric split ===
// Phase 1 (kt 0..63): acc += Ahi @ Blo; then acc *= 2^-10 once;
// Phase 2 (kt 64..127): acc += Ahi @ Bhi.
// CTA 128x128, BK=32, 3-stage cp.async pipeline, 4 warps (2m x 2n),
// warp tile 64x64, mma.m16n8k16, 1 syncthreads per k-iter.
// Swizzle: 16B unit u of row r stored at u ^ ((r>>1)&3).
#define BM 128
#define BN 128
#define BK 32
#define KSTEPS 128   // 2 terms * 64 k-chunks (lo first, then hi)
#define STAGES 3

__device__ __forceinline__ uint32_t smem_u32(const void* p) {
    uint32_t a;
    asm("{ .reg .u64 t; cvta.to.shared.u64 t, %1; cvt.u32.u64 %0, t; }" : "=r"(a) : "l"(p));
    return a;
}
__device__ __forceinline__ void cp_async16(uint32_t dst, const void* src) {
    asm volatile("cp.async.cg.shared.global [%0], [%1], 16;"
                 :: "r"(dst), "l"(__cvta_generic_to_global(src)) : "memory");
}
__device__ __forceinline__ void ldsm_x4(uint32_t* r, uint32_t addr) {
    asm volatile("ldmatrix.sync.aligned.m8n8.x4.shared.b16 {%0,%1,%2,%3}, [%4];"
                 : "=r"(r[0]), "=r"(r[1]), "=r"(r[2]), "=r"(r[3]) : "r"(addr));
}
__device__ __forceinline__ void mma16816(float* d, const uint32_t* a, uint32_t b0, uint32_t b1) {
    asm volatile("mma.sync.aligned.m16n8k16.row.col.f32.f16.f16.f32 "
                 "{%0,%1,%2,%3}, {%4,%5,%6,%7}, {%8,%9}, {%0,%1,%2,%3};"
                 : "+f"(d[0]), "+f"(d[1]), "+f"(d[2]), "+f"(d[3])
                 : "r"(a[0]), "r"(a[1]), "r"(a[2]), "r"(a[3]), "r"(b0), "r"(b1));
}

__global__ void __launch_bounds__(128, 2) k_gemm_mma(float* __restrict__ C0) {
    __shared__ __align__(1024) __half As[STAGES][BM * BK];  // 3 x 8KB
    __shared__ __align__(1024) __half Bs[STAGES][BN * BK];  // 3 x 8KB

    const int tid = threadIdx.x, lane = tid & 31, w = tid >> 5;
    const int wm = w >> 1, wn = w & 1;
    const int g = blockIdx.z, bm = blockIdx.y, bn = blockIdx.x;
    const size_t gbase = (size_t)g * SDIM * SDIM;

    const uint32_t sA = smem_u32(As), sB = smem_u32(Bs);

    float acc[4][8][4];
    #pragma unroll
    for (int i = 0; i < 4; i++)
        #pragma unroll
        for (int j = 0; j < 8; j++)
            #pragma unroll
            for (int q = 0; q < 4; q++) acc[i][j][q] = 0.0f;

    const int ldRow = tid >> 2, ldUnit = tid & 3;   // 32 rows x 4 units per pass

    auto issue = [&](int kt, int st) {
        const int kk = kt & 63;
        const __half* Abase = g_Ahi + gbase + (size_t)(bm * 128) * SDIM + kk * 32;
        const __half* Bbase = ((kt < 64) ? g_Btlo : g_Bthi)
                              + gbase + (size_t)(bn * 128) * SDIM + kk * 32;
        #pragma unroll
        for (int it = 0; it < 4; it++) {
            const int r = ldRow + it * 32;
            const uint32_t du = (uint32_t)(ldUnit ^ ((r >> 1) & 3));
            cp_async16(sA + (uint32_t)st * (BM * BK * 2) + (uint32_t)r * 64 + du * 16,
                       Abase + (size_t)r * SDIM + ldUnit * 8);
            cp_async16(sB + (uint32_t)st * (BN * BK * 2) + (uint32_t)r * 64 + du * 16,
                       Bbase + (size_t)r * SDIM + ldUnit * 8);
        }
        asm volatile("cp.async.commit_group;" ::: "memory");
    };

    issue(0, 0);
    issue(1, 1);

    for (int kt = 0; kt < KSTEPS; kt++) {
        if (kt < KSTEPS - 1)
            asm volatile("cp.async.wait_group 1;" ::: "memory");
        else
            asm volatile("cp.async.wait_group 0;" ::: "memory");
        __syncthreads();   // stage kt%3 visible to all; all reads of kt-1 done

        // Phase boundary: lo-term partial sum complete -> scale by 2^-10 once.
        if (kt == 64) {
            #pragma unroll
            for (int i = 0; i < 4; i++)
                #pragma unroll
                for (int j = 0; j < 8; j++)
                    #pragma unroll
                    for (int q = 0; q < 4; q++) acc[i][j][q] *= 0.0009765625f;
        }

        const int st = kt % STAGES;
        const uint32_t aSt = sA + (uint32_t)st * (BM * BK * 2);
        const uint32_t bSt = sB + (uint32_t)st * (BN * BK * 2);
        #pragma unroll
        for (int k16 = 0; k16 < 2; k16++) {
            const int ku = k16 * 2 + (lane >> 4);
            uint32_t a[4][4];
            #pragma unroll
            for (int mt = 0; mt < 4; mt++) {
                const int r = wm * 64 + mt * 16 + (lane & 15);
                ldsm_x4(a[mt], aSt + (uint32_t)r * 64 + (uint32_t)((ku ^ ((r >> 1) & 3)) * 16));
            }
            uint32_t b[4][4];
            #pragma unroll
            for (int ng = 0; ng < 4; ng++) {
                const int r = wn * 64 + ng * 16 + (lane & 15);
                ldsm_x4(b[ng], bSt + (uint32_t)r * 64 + (uint32_t)((ku ^ ((r >> 1) & 3)) * 16));
            }
            #pragma unroll
            for (int mt = 0; mt < 4; mt++)
                #pragma unroll
                for (int nt = 0; nt < 8; nt++)
                    mma16816(acc[mt][nt], a[mt], b[nt >> 1][nt & 1], b[nt >> 1][(nt & 1) + 2]);
        }
        // refill stage (kt+2)%3 == (kt-1)%3: all reads of it finished before
        // this iteration's __syncthreads, so the overwrite is safe.
        if (kt + 2 < KSTEPS) issue(kt + 2, (kt + 2) % STAGES);
    }

    // epilogue
    float* C = C0 + gbase;
    #pragma unroll
    for (int mt = 0; mt < 4; mt++)
        #pragma unroll
        for (int nt = 0; nt < 8; nt++) {
            const int row = bm * 128 + wm * 64 + mt * 16 + (lane >> 2);
            const int col = bn * 128 + wn * 64 + nt * 8 + (lane & 3) * 2;
            *reinterpret_cast<float2*>(C + (size_t)row * SDIM + col) =
                make_float2(acc[mt][nt][0], acc[mt][nt][1]);
            *reinterpret_cast<float2*>(C + (size_t)(row + 8) * SDIM + col) =
                make_float2(acc[mt][nt][2], acc[mt][nt][3]);
        }
}

// ===================== launch ==============================================
extern "C" void kernel_launch(void* const* d_in, const int* in_sizes, int n_in,
                              void* d_out, int out_size) {
    const float* x1 = (const float*)d_in[0];
    const float* x2 = (const float*)d_in[1];
    float* out = (float*)d_out;
    const float4* x1v = (const float4*)x1;
    const float4* x2v = (const float4*)x2;

    // One-time stream/event resources for fork-join overlap (work per call is
    // identical every call; only resource handles are persistent).
    static cudaStream_t s2 = nullptr;
    static cudaEvent_t evF = nullptr, evJ = nullptr;
    static int ready = 0;
    if (ready == 0) {
        bool ok = (cudaStreamCreateWithFlags(&s2, cudaStreamNonBlocking) == cudaSuccess) &&
                  (cudaEventCreateWithFlags(&evF, cudaEventDisableTiming) == cudaSuccess) &&
                  (cudaEventCreateWithFlags(&evJ, cudaEventDisableTiming) == cudaSuccess);
        ready = ok ? 1 : -1;
    }

    cudaStream_t sStats = (ready == 1) ? s2 : (cudaStream_t)0;
    if (ready == 1) {
        cudaEventRecord(evF, 0);
        cudaStreamWaitEvent(s2, evF, 0);
    }

    // ---- main stream: conversions + tensor-core GEMM -> out region 0 ----
    k_convA<<<1024, 256>>>(x1v);
    k_convB<<<dim3(64, 64, NBATCH), dim3(32, 8)>>>(x2);
    k_gemm_mma<<<dim3(16, 16, NBATCH), 128>>>(out);

    // ---- stats stream: quantile + quantize -> out regions 1, 2 ----
    k_init<<<1, 256, 0, sStats>>>();
    for (int shift = 24; shift >= 0; shift -= 8) {
        k_hist<<<dim3(512, 2), 256, 0, sStats>>>(x1v, x2v, shift);
        k_scan<<<1, 256, 0, sStats>>>(shift);
    }
    k_maxres<<<dim3(1024, 2), 256, 0, sStats>>>(x1v, x2v);
    k_scale<<<1, 32, 0, sStats>>>();
    k_quant<<<dim3(1024, 2), 256, 0, sStats>>>(x1v, x2v, (float4*)out);

    if (ready == 1) {
        cudaEventRecord(evJ, s2);
        cudaStreamWaitEvent((cudaStream_t)0, evJ, 0);
    }
}

// round 9
// speedup vs baseline: 4.2108x; 1.5550x over previous
#include <cuda_runtime.h>
#include <cuda_fp16.h>
#include <cstdint>

// Problem constants (B=2, H=8, S=2048, D=2048)
#define N_ELEM   67108864    // elements per input tensor
#define N0       33554432    // elements in x[0]
#define K_IDX    33218888u   // exact f32 quantile index of |x[0]| ascending
#define SDIM     2048
#define NBATCH   16

// ===================== scratch: fp16 tensors (linear) =======================
__device__ __align__(1024) __half g_Ahi[N_ELEM];   // [g][m][k]  fp16(x1)
__device__ __align__(1024) __half g_Bthi[N_ELEM];  // [g][n][k]  fp16(x2^T)

// ===================== stats state (re-initialized per launch) ==============
__device__ unsigned g_hist[2][256];
__device__ unsigned g_pref[2];
__device__ unsigned g_krem[2];
__device__ unsigned g_taub[2];
__device__ unsigned g_maxres[2];
__device__ float    g_scale[2];

__global__ void k_init() {
    int i = threadIdx.x;
    g_hist[0][i] = 0; g_hist[1][i] = 0;
    if (i < 2) { g_pref[i] = 0; g_krem[i] = K_IDX; g_maxres[i] = 0; }
}

__global__ void __launch_bounds__(256) k_hist(const float4* __restrict__ x1,
                                              const float4* __restrict__ x2,
                                              int shift) {
    const int t = blockIdx.y;
    const float4* __restrict__ x = t ? x2 : x1;
    __shared__ unsigned sh[256];
    const int tid = threadIdx.x;
    sh[tid] = 0;
    __syncthreads();
    const unsigned pref = g_pref[t];
    const int n4 = N0 / 4;
    const int stride = gridDim.x * blockDim.x;
    for (int i = blockIdx.x * blockDim.x + tid; i < n4; i += stride) {
        float4 v = x[i];
        const float* f = reinterpret_cast<const float*>(&v);
        #pragma unroll
        for (int j = 0; j < 4; j++) {
            unsigned u = __float_as_uint(f[j]) & 0x7fffffffu;
            bool ok = (shift == 24) || ((u >> (shift + 8)) == pref);
            unsigned bal = __ballot_sync(0xffffffffu, ok);
            if (ok) {
                unsigned b = (u >> shift) & 255u;
                unsigned peers = __match_any_sync(bal, b);
                if ((__ffs(peers) - 1) == (tid & 31))
                    atomicAdd(&sh[b], __popc(peers));
            }
        }
    }
    __syncthreads();
    if (sh[tid]) atomicAdd(&g_hist[t][tid], sh[tid]);
}

__global__ void k_scan(int shift) {
    const int tid = threadIdx.x;
    if (tid < 2) {
        const int t = tid;
        unsigned k = g_krem[t], c = 0, chosen = 255;
        for (int b = 0; b < 256; b++) {
            unsigned h = g_hist[t][b];
            if (c + h > k) { chosen = (unsigned)b; break; }
            c += h;
        }
        g_krem[t] = k - c;
        unsigned p = (g_pref[t] << 8) | chosen;
        g_pref[t] = p;
        if (shift == 0) g_taub[t] = p;
    }
    __syncthreads();
    g_hist[0][tid] = 0; g_hist[1][tid] = 0;
}

__global__ void __launch_bounds__(256) k_maxres(const float4* __restrict__ x1,
                                                const float4* __restrict__ x2) {
    const int t = blockIdx.y;
    const float4* __restrict__ x = t ? x2 : x1;
    const unsigned taub = g_taub[t];
    const int tid = threadIdx.x;
    unsigned m = 0;
    const int n4 = N_ELEM / 4;
    const int stride = gridDim.x * blockDim.x;
    for (int i = blockIdx.x * blockDim.x + tid; i < n4; i += stride) {
        float4 v = x[i];
        const float* f = reinterpret_cast<const float*>(&v);
        #pragma unroll
        for (int j = 0; j < 4; j++) {
            unsigned u = __float_as_uint(f[j]) & 0x7fffffffu;
            if (u < taub) m = max(m, u);
        }
    }
    m = __reduce_max_sync(0xffffffffu, m);
    __shared__ unsigned sm[8];
    if ((tid & 31) == 0) sm[tid >> 5] = m;
    __syncthreads();
    if (tid == 0) {
        #pragma unroll
        for (int w = 1; w < 8; w++) m = max(m, sm[w]);
        atomicMax(&g_maxres[t], m);
    }
}

__global__ void k_scale() {
    int t = threadIdx.x;
    if (t < 2) g_scale[t] = __fdiv_rn(__uint_as_float(g_maxres[t]), 127.0f);
}

__global__ void __launch_bounds__(256) k_quant(const float4* __restrict__ x1,
                                               const float4* __restrict__ x2,
                                               float4* __restrict__ out) {
    const int t = blockIdx.y;
    const float4* __restrict__ x = t ? x2 : x1;
    float4* __restrict__ o = out + (size_t)(1 + t) * (N_ELEM / 4);
    const float tau = __uint_as_float(g_taub[t]);
    const float scale = g_scale[t];
    const int n4 = N_ELEM / 4;
    const int stride = gridDim.x * blockDim.x;
    for (int i = blockIdx.x * blockDim.x + threadIdx.x; i < n4; i += stride) {
        float4 v = x[i];
        float* f = reinterpret_cast<float*>(&v);
        #pragma unroll
        for (int j = 0; j < 4; j++) {
            float a = fabsf(f[j]);
            if (a < tau) {
                float q = rintf(__fdiv_rn(f[j], scale));
                q = fminf(fmaxf(q, -128.0f), 127.0f);
                f[j] = q * scale;
            }
        }
        o[i] = v;
    }
}

// half2 -> u32 bit cast
__device__ __forceinline__ uint32_t h2_as_u32(__half2 h) {
    union { __half2 h; uint32_t u; } c;
    c.h = h;
    return c.u;
}

// ===== A: f32 [g][m][k] -> fp16 (linear) ====================================
__global__ void __launch_bounds__(256) k_convA(const float4* __restrict__ x) {
    const int stride = gridDim.x * blockDim.x;
    for (int i = blockIdx.x * blockDim.x + threadIdx.x; i < N_ELEM / 8; i += stride) {
        float4 v0 = x[2 * i], v1 = x[2 * i + 1];
        uint32_t h[4];
        h[0] = h2_as_u32(__floats2half2_rn(v0.x, v0.y));
        h[1] = h2_as_u32(__floats2half2_rn(v0.z, v0.w));
        h[2] = h2_as_u32(__floats2half2_rn(v1.x, v1.y));
        h[3] = h2_as_u32(__floats2half2_rn(v1.z, v1.w));
        reinterpret_cast<uint4*>(g_Ahi)[i] = make_uint4(h[0], h[1], h[2], h[3]);
    }
}

// ===== B: f32 [g][k][n] -> transposed fp16 [g][n][k] ========================
__global__ void __launch_bounds__(256) k_convB(const float* __restrict__ x) {
    __shared__ float t[32][33];
    const int g = blockIdx.z;
    const float* B = x + (size_t)g * SDIM * SDIM;
    const int n0 = blockIdx.x * 32, k0 = blockIdx.y * 32;
    const int tx = threadIdx.x, ty = threadIdx.y;
    #pragma unroll
    for (int j = 0; j < 32; j += 8)
        t[ty + j][tx] = B[(size_t)(k0 + ty + j) * SDIM + n0 + tx];
    __syncthreads();
    #pragma unroll
    for (int j = 0; j < 32; j += 8) {
        int n = n0 + ty + j, k = k0 + tx;
        g_Bthi[(size_t)g * SDIM * SDIM + (size_t)n * SDIM + k] =
            __float2half_rn(t[tx][ty + j]);
    }
}

// ===== tensor-core GEMM via mma.sync (HMMA), single fp16 term ===============
// CTA 128x128, BK=32, 3-stage cp.async pipeline, 4 warps (2m x 2n),
// warp tile 64x64, mma.m16n8k16, 1 syncthreads per k-iter.
// Swizzle: 16B unit u of row r stored at u ^ ((r>>1)&3).
#define BM 128
#define BN 128
#define BK 32
#define KSTEPS 64    // 2048 / BK
#define STAGES 3

__device__ __forceinline__ uint32_t smem_u32(const void* p) {
    uint32_t a;
    asm("{ .reg .u64 t; cvta.to.shared.u64 t, %1; cvt.u32.u64 %0, t; }" : "=r"(a) : "l"(p));
    return a;
}
__device__ __forceinline__ void cp_async16(uint32_t dst, const void* src) {
    asm volatile("cp.async.cg.shared.global [%0], [%1], 16;"
                 :: "r"(dst), "l"(__cvta_generic_to_global(src)) : "memory");
}
__device__ __forceinline__ void ldsm_x4(uint32_t* r, uint32_t addr) {
    asm volatile("ldmatrix.sync.aligned.m8n8.x4.shared.b16 {%0,%1,%2,%3}, [%4];"
                 : "=r"(r[0]), "=r"(r[1]), "=r"(r[2]), "=r"(r[3]) : "r"(addr));
}
__device__ __forceinline__ void mma16816(float* d, const uint32_t* a, uint32_t b0, uint32_t b1) {
    asm volatile("mma.sync.aligned.m16n8k16.row.col.f32.f16.f16.f32 "
                 "{%0,%1,%2,%3}, {%4,%5,%6,%7}, {%8,%9}, {%0,%1,%2,%3};"
                 : "+f"(d[0]), "+f"(d[1]), "+f"(d[2]), "+f"(d[3])
                 : "r"(a[0]), "r"(a[1]), "r"(a[2]), "r"(a[3]), "r"(b0), "r"(b1));
}

__global__ void __launch_bounds__(128, 2) k_gemm_mma(float* __restrict__ C0) {
    __shared__ __align__(1024) __half As[STAGES][BM * BK];  // 3 x 8KB
    __shared__ __align__(1024) __half Bs[STAGES][BN * BK];  // 3 x 8KB

    const int tid = threadIdx.x, lane = tid & 31, w = tid >> 5;
    const int wm = w >> 1, wn = w & 1;
    const int g = blockIdx.z, bm = blockIdx.y, bn = blockIdx.x;
    const size_t gbase = (size_t)g * SDIM * SDIM;

    const uint32_t sA = smem_u32(As), sB = smem_u32(Bs);

    float acc[4][8][4];
    #pragma unroll
    for (int i = 0; i < 4; i++)
        #pragma unroll
        for (int j = 0; j < 8; j++)
            #pragma unroll
            for (int q = 0; q < 4; q++) acc[i][j][q] = 0.0f;

    const int ldRow = tid >> 2, ldUnit = tid & 3;   // 32 rows x 4 units per pass

    auto issue = [&](int kt, int st) {
        const __half* Abase = g_Ahi  + gbase + (size_t)(bm * 128) * SDIM + kt * 32;
        const __half* Bbase = g_Bthi + gbase + (size_t)(bn * 128) * SDIM + kt * 32;
        #pragma unroll
        for (int it = 0; it < 4; it++) {
            const int r = ldRow + it * 32;
            const uint32_t du = (uint32_t)(ldUnit ^ ((r >> 1) & 3));
            cp_async16(sA + (uint32_t)st * (BM * BK * 2) + (uint32_t)r * 64 + du * 16,
                       Abase + (size_t)r * SDIM + ldUnit * 8);
            cp_async16(sB + (uint32_t)st * (BN * BK * 2) + (uint32_t)r * 64 + du * 16,
                       Bbase + (size_t)r * SDIM + ldUnit * 8);
        }
        asm volatile("cp.async.commit_group;" ::: "memory");
    };

    issue(0, 0);
    issue(1, 1);

    for (int kt = 0; kt < KSTEPS; kt++) {
        if (kt < KSTEPS - 1)
            asm volatile("cp.async.wait_group 1;" ::: "memory");
        else
            asm volatile("cp.async.wait_group 0;" ::: "memory");
        __syncthreads();   // stage kt%3 visible to all; all reads of kt-1 done

        const int st = kt % STAGES;
        const uint32_t aSt = sA + (uint32_t)st * (BM * BK * 2);
        const uint32_t bSt = sB + (uint32_t)st * (BN * BK * 2);
        #pragma unroll
        for (int k16 = 0; k16 < 2; k16++) {
            const int ku = k16 * 2 + (lane >> 4);
            uint32_t a[4][4];
            #pragma unroll
            for (int mt = 0; mt < 4; mt++) {
                const int r = wm * 64 + mt * 16 + (lane & 15);
                ldsm_x4(a[mt], aSt + (uint32_t)r * 64 + (uint32_t)((ku ^ ((r >> 1) & 3)) * 16));
            }
            uint32_t b[4][4];
            #pragma unroll
            for (int ng = 0; ng < 4; ng++) {
                const int r = wn * 64 + ng * 16 + (lane & 15);
                ldsm_x4(b[ng], bSt + (uint32_t)r * 64 + (uint32_t)((ku ^ ((r >> 1) & 3)) * 16));
            }
            #pragma unroll
            for (int mt = 0; mt < 4; mt++)
                #pragma unroll
                for (int nt = 0; nt < 8; nt++)
                    mma16816(acc[mt][nt], a[mt], b[nt >> 1][nt & 1], b[nt >> 1][(nt & 1) + 2]);
        }
        // refill stage (kt+2)%3 == (kt-1)%3: all reads of it finished before
        // this iteration's __syncthreads, so the overwrite is safe.
        if (kt + 2 < KSTEPS) issue(kt + 2, (kt + 2) % STAGES);
    }

    // epilogue
    float* C = C0 + gbase;
    #pragma unroll
    for (int mt = 0; mt < 4; mt++)
        #pragma unroll
        for (int nt = 0; nt < 8; nt++) {
            const int row = bm * 128 + wm * 64 + mt * 16 + (lane >> 2);
            const int col = bn * 128 + wn * 64 + nt * 8 + (lane & 3) * 2;
            *reinterpret_cast<float2*>(C + (size_t)row * SDIM + col) =
                make_float2(acc[mt][nt][0], acc[mt][nt][1]);
            *reinterpret_cast<float2*>(C + (size_t)(row + 8) * SDIM + col) =
                make_float2(acc[mt][nt][2], acc[mt][nt][3]);
        }
}

// ===================== launch ==============================================
extern "C" void kernel_launch(void* const* d_in, const int* in_sizes, int n_in,
                              void* d_out, int out_size) {
    const float* x1 = (const float*)d_in[0];
    const float* x2 = (const float*)d_in[1];
    float* out = (float*)d_out;
    const float4* x1v = (const float4*)x1;
    const float4* x2v = (const float4*)x2;

    // One-time stream/event resources for fork-join overlap (work per call is
    // identical every call; only resource handles are persistent).
    static cudaStream_t s2 = nullptr;
    static cudaEvent_t evF = nullptr, evJ = nullptr;
    static int ready = 0;
    if (ready == 0) {
        bool ok = (cudaStreamCreateWithFlags(&s2, cudaStreamNonBlocking) == cudaSuccess) &&
                  (cudaEventCreateWithFlags(&evF, cudaEventDisableTiming) == cudaSuccess) &&
                  (cudaEventCreateWithFlags(&evJ, cudaEventDisableTiming) == cudaSuccess);
        ready = ok ? 1 : -1;
    }

    cudaStream_t sStats = (ready == 1) ? s2 : (cudaStream_t)0;
    if (ready == 1) {
        cudaEventRecord(evF, 0);
        cudaStreamWaitEvent(s2, evF, 0);
    }

    // ---- main stream: conversions + tensor-core GEMM -> out region 0 ----
    k_convA<<<1024, 256>>>(x1v);
    k_convB<<<dim3(64, 64, NBATCH), dim3(32, 8)>>>(x2);
    k_gemm_mma<<<dim3(16, 16, NBATCH), 128>>>(out);

    // ---- stats stream: quantile + quantize -> out regions 1, 2 ----
    k_init<<<1, 256, 0, sStats>>>();
    for (int shift = 24; shift >= 0; shift -= 8) {
        k_hist<<<dim3(512, 2), 256, 0, sStats>>>(x1v, x2v, shift);
        k_scan<<<1, 256, 0, sStats>>>(shift);
    }
    k_maxres<<<dim3(1024, 2), 256, 0, sStats>>>(x1v, x2v);
    k_scale<<<1, 32, 0, sStats>>>();
    k_quant<<<dim3(1024, 2), 256, 0, sStats>>>(x1v, x2v, (float4*)out);

    if (ready == 1) {
        cudaEventRecord(evJ, s2);
        cudaStreamWaitEvent((cudaStream_t)0, evJ, 0);
    }
}